// round 3
// baseline (speedup 1.0000x reference)
#include <cuda_runtime.h>
#include <cuda_fp16.h>
#include <cstdint>

#define HDIM     128
#define INDIM    13
#define B_TOTAL  262144
#define TILE_M   128
#define NBT      (B_TOTAL / TILE_M)
#define NTHREADS 256

// packed weights: [512 cols][144 k] fp16, col = nh*256 + wn*64 + gate*16 + jl
__device__ __half g_W[512 * 144];
__device__ float  g_bias[512];

struct WP { const float *Wx[4], *bx[4], *Wh[4], *bh[4]; };

__global__ void prep_kernel(WP p) {
    int idx = blockIdx.x * blockDim.x + threadIdx.x;
    if (idx < 512) {
        int r = idx & 255, nh = idx >> 8;
        int wn = r >> 6, gate = (r >> 4) & 3, jl = r & 15;
        int j = nh * 64 + wn * 16 + jl;
        g_bias[idx] = p.bx[gate][j] + p.bh[gate][j];
    }
    if (idx < 512 * 144) {
        int col = idx / 144, k = idx - col * 144;
        int r = col & 255, nh = col >> 8;
        int wn = r >> 6, gate = (r >> 4) & 3, jl = r & 15;
        int j = nh * 64 + wn * 16 + jl;
        float v = 0.f;
        if (k < INDIM)               v = p.Wx[gate][j * INDIM + k];
        else if (k >= 16 && k < 144) v = p.Wh[gate][j * HDIM + (k - 16)];
        g_W[col * 144 + k] = __float2half_rn(v);
    }
}

__device__ __forceinline__ float fsig(float x) { return __fdividef(1.0f, 1.0f + __expf(-x)); }
__device__ __forceinline__ float htanh(float x) { return fminf(fmaxf(x, -1.f), 1.f); }

// smem layout (bytes from base):
//  A: 128 x 152 fp16               = 38912
//  B: 256 x 152 fp16               = 77824   (weights half, per-CTA constant)
//  bias: 256 f32                   = 1024
//  cs: 128 x 65 f32                = 33280   (c staging, in-place c_in -> c_t)
//  hs: 128 x 65 f32                = 33280
#define PITCH   152
#define SM_A    0u
#define SM_B    38912u
#define SM_BIAS 116736u
#define SM_CS   117760u
#define SM_HS   151040u
#define SMEM_BYTES 184320u

__global__ void __launch_bounds__(NTHREADS, 1)
lstm_kernel(const float* __restrict__ x_in, const float* __restrict__ h_in,
            const float* __restrict__ c_in, float* __restrict__ out)
{
    extern __shared__ char sm[];
    __half* As = (__half*)(sm + SM_A);
    __half* Bs = (__half*)(sm + SM_B);
    float*  bs = (float*)(sm + SM_BIAS);
    float*  cs = (float*)(sm + SM_CS);
    float*  hs = (float*)(sm + SM_HS);

    const int tid  = threadIdx.x;
    const int wid  = tid >> 5;
    const int lane = tid & 31;
    const int q    = lane & 3;       // t%4
    const int gid  = lane >> 2;      // t/4
    const int wm   = wid & 1;        // M half (rows 64*wm ..)
    const int wn   = wid >> 1;       // 0..3, j block of 16

    const int nh     = blockIdx.x & 1;
    const int cidx   = blockIdx.x >> 1;
    const int npairs = gridDim.x >> 1;

    // ---- stage weights half + bias once ----
    {
        const uint32_t* wsrc = (const uint32_t*)g_W + nh * 18432;
        for (int i = tid; i < 256 * 72; i += NTHREADS) {
            int col = i / 72, kk = i - col * 72;
            *((uint32_t*)Bs + col * (PITCH / 2) + kk) = wsrc[col * 72 + kk];
        }
        for (int i = tid; i < 256; i += NTHREADS) bs[i] = g_bias[nh * 256 + i];
    }
    __syncthreads();

    // per-thread bias init values (column-only): binit[nt][e]
    float binit[8][2];
    #pragma unroll
    for (int nt = 0; nt < 8; nt++) {
        binit[nt][0] = bs[wn * 64 + nt * 8 + 2 * q + 0];
        binit[nt][1] = bs[wn * 64 + nt * 8 + 2 * q + 1];
    }

    float* out_h  = out;
    float* out_h2 = out + (size_t)B_TOTAL * HDIM;
    float* out_c  = out + (size_t)2 * B_TOTAL * HDIM;

    for (int bt = cidx; bt < NBT; bt += npairs) {
        const int rowbase = bt * TILE_M;
        __syncthreads();   // prior tile's store phase done with staging / A free

        // ---- A: h part (k 16..143), fp32 -> fp16 ----
        for (int i = tid; i < 128 * 32; i += NTHREADS) {
            int r = i >> 5, kq = i & 31;
            float4 v = ((const float4*)(h_in + (size_t)(rowbase + r) * HDIM))[kq];
            __half* ap = As + r * PITCH + 16 + kq * 4;
            *(__half2*)(ap)     = __floats2half2_rn(v.x, v.y);
            *(__half2*)(ap + 2) = __floats2half2_rn(v.z, v.w);
        }
        // ---- A: x part (k 0..15, 13 real + 3 zero) ----
        for (int i = tid; i < 128 * 16; i += NTHREADS) {
            int r = i >> 4, c = i & 15;
            float v = (c < INDIM) ? x_in[(size_t)(rowbase + r) * INDIM + c] : 0.f;
            As[r * PITCH + c] = __float2half_rn(v);
        }
        // ---- c preload (coalesced) ----
        for (int i = tid; i < 128 * 16; i += NTHREADS) {
            int r = i >> 4, p4 = (i & 15) * 4;
            float4 v = *(const float4*)(c_in + (size_t)(rowbase + r) * HDIM + nh * 64 + p4);
            cs[r * 65 + p4] = v.x; cs[r * 65 + p4 + 1] = v.y;
            cs[r * 65 + p4 + 2] = v.z; cs[r * 65 + p4 + 3] = v.w;
        }
        __syncthreads();

        // ---- MMA: warp tile 64 rows x 64 cols, K = 144 ----
        float acc[4][8][4];
        #pragma unroll
        for (int mt = 0; mt < 4; mt++)
            #pragma unroll
            for (int nt = 0; nt < 8; nt++) {
                acc[mt][nt][0] = binit[nt][0];
                acc[mt][nt][1] = binit[nt][1];
                acc[mt][nt][2] = binit[nt][0];
                acc[mt][nt][3] = binit[nt][1];
            }

        #pragma unroll 1
        for (int ks = 0; ks < 9; ks++) {
            const int kb = ks * 16 + 2 * q;
            uint32_t af[4][4];
            #pragma unroll
            for (int mt = 0; mt < 4; mt++) {
                const __half* ap = As + (wm * 64 + mt * 16 + gid) * PITCH + kb;
                af[mt][0] = *(const uint32_t*)(ap);
                af[mt][1] = *(const uint32_t*)(ap + 8 * PITCH);
                af[mt][2] = *(const uint32_t*)(ap + 8);
                af[mt][3] = *(const uint32_t*)(ap + 8 * PITCH + 8);
            }
            uint32_t bf[8][2];
            #pragma unroll
            for (int nt = 0; nt < 8; nt++) {
                const __half* bp = Bs + (wn * 64 + nt * 8 + gid) * PITCH + kb;
                bf[nt][0] = *(const uint32_t*)(bp);
                bf[nt][1] = *(const uint32_t*)(bp + 8);
            }
            #pragma unroll
            for (int mt = 0; mt < 4; mt++)
                #pragma unroll
                for (int nt = 0; nt < 8; nt++) {
                    asm("mma.sync.aligned.m16n8k16.row.col.f32.f16.f16.f32 "
                        "{%0,%1,%2,%3}, {%4,%5,%6,%7}, {%8,%9}, {%0,%1,%2,%3};"
                        : "+f"(acc[mt][nt][0]), "+f"(acc[mt][nt][1]),
                          "+f"(acc[mt][nt][2]), "+f"(acc[mt][nt][3])
                        : "r"(af[mt][0]), "r"(af[mt][1]), "r"(af[mt][2]), "r"(af[mt][3]),
                          "r"(bf[nt][0]), "r"(bf[nt][1]));
                }
        }

        // ---- epilogue: all 4 gates of (row, j) live in this thread ----
        #pragma unroll
        for (int mt = 0; mt < 4; mt++) {
            #pragma unroll
            for (int b = 0; b < 2; b++) {
                #pragma unroll
                for (int e = 0; e < 2; e++) {
                    const int jloc = wn * 16 + 8 * b + 2 * q + e;
                    #pragma unroll
                    for (int rs = 0; rs < 2; rs++) {
                        const int row = wm * 64 + mt * 16 + gid + 8 * rs;
                        const int ci  = rs * 2 + e;
                        float pi = acc[mt][0 + b][ci];
                        float pf = acc[mt][2 + b][ci];
                        float pg = acc[mt][4 + b][ci];
                        float po = acc[mt][6 + b][ci];
                        float it = fsig(pi), ft = fsig(pf), ot = fsig(po);
                        float gt = htanh(pg);
                        float ct = ft * cs[row * 65 + jloc] + it * gt;
                        float ht = ot * htanh(ct);
                        cs[row * 65 + jloc] = ct;
                        hs[row * 65 + jloc] = ht;
                    }
                }
            }
        }
        __syncthreads();

        // ---- coalesced float4 stores via staging ----
        for (int i = tid; i < 128 * 16; i += NTHREADS) {
            int r = i >> 4, p4 = (i & 15) * 4;
            float4 v = make_float4(hs[r * 65 + p4], hs[r * 65 + p4 + 1],
                                   hs[r * 65 + p4 + 2], hs[r * 65 + p4 + 3]);
            float4 w = make_float4(cs[r * 65 + p4], cs[r * 65 + p4 + 1],
                                   cs[r * 65 + p4 + 2], cs[r * 65 + p4 + 3]);
            size_t o = (size_t)(rowbase + r) * HDIM + nh * 64 + p4;
            *(float4*)(out_h + o)  = v;
            *(float4*)(out_h2 + o) = v;
            *(float4*)(out_c + o)  = w;
        }
    }
}

extern "C" void kernel_launch(void* const* d_in, const int* in_sizes, int n_in,
                              void* d_out, int out_size) {
    WP p;
    for (int g = 0; g < 4; g++) {
        p.Wx[g] = (const float*)d_in[3 + 4 * g];
        p.bx[g] = (const float*)d_in[4 + 4 * g];
        p.Wh[g] = (const float*)d_in[5 + 4 * g];
        p.bh[g] = (const float*)d_in[6 + 4 * g];
    }
    prep_kernel<<<(512 * 144 + 255) / 256, 256>>>(p);

    int dev = 0, sms = 0;
    cudaGetDevice(&dev);
    cudaDeviceGetAttribute(&sms, cudaDevAttrMultiProcessorCount, dev);
    if (sms <= 0) sms = 148;
    int grid = sms & ~1;
    cudaFuncSetAttribute(lstm_kernel, cudaFuncAttributeMaxDynamicSharedMemorySize, SMEM_BYTES);
    lstm_kernel<<<grid, NTHREADS, SMEM_BYTES>>>(
        (const float*)d_in[0], (const float*)d_in[1], (const float*)d_in[2], (float*)d_out);
}

// round 4
// speedup vs baseline: 1.4162x; 1.4162x over previous
#include <cuda_runtime.h>
#include <cuda_fp16.h>
#include <cstdint>

#define HDIM     128
#define INDIM    13
#define B_TOTAL  262144
#define TILE_M   128
#define NBT      (B_TOTAL / TILE_M)
#define NTHREADS 512

// packed weights: [512 cols][144 k] fp16, col = nh*256 + wn*64 + gate*16 + jl
__device__ __half g_W[512 * 144];
__device__ float  g_bias[512];

struct WP { const float *Wx[4], *bx[4], *Wh[4], *bh[4]; };

__global__ void prep_kernel(WP p) {
    int idx = blockIdx.x * blockDim.x + threadIdx.x;
    if (idx < 512) {
        int r = idx & 255, nh = idx >> 8;
        int wn = r >> 6, gate = (r >> 4) & 3, jl = r & 15;
        int j = nh * 64 + wn * 16 + jl;
        g_bias[idx] = p.bx[gate][j] + p.bh[gate][j];
    }
    if (idx < 512 * 144) {
        int col = idx / 144, k = idx - col * 144;
        int r = col & 255, nh = col >> 8;
        int wn = r >> 6, gate = (r >> 4) & 3, jl = r & 15;
        int j = nh * 64 + wn * 16 + jl;
        float v = 0.f;
        if (k < INDIM)               v = p.Wx[gate][j * INDIM + k];
        else if (k >= 16 && k < 144) v = p.Wh[gate][j * HDIM + (k - 16)];
        g_W[col * 144 + k] = __float2half_rn(v);
    }
}

__device__ __forceinline__ float fsig(float x) { return __fdividef(1.0f, 1.0f + __expf(-x)); }
__device__ __forceinline__ float htanh(float x) { return fminf(fmaxf(x, -1.f), 1.f); }

// smem layout (bytes):
//  As: 128 x 152 fp16  = 38912
//  Bs: 256 x 152 fp16  = 77824
//  bias: 256 f32       = 1024
//  cs: 128 x 68 f32    = 34816   (c staging, in-place c_in -> c_t)
//  hs: 128 x 68 f32    = 34816
#define PITCH    152
#define CPITCH   68
#define SM_A     0u
#define SM_B     38912u
#define SM_BIAS  116736u
#define SM_CS    117760u
#define SM_HS    152576u
#define SMEM_BYTES 187392u

__global__ void __launch_bounds__(NTHREADS, 1)
lstm_kernel(const float* __restrict__ x_in, const float* __restrict__ h_in,
            const float* __restrict__ c_in, float* __restrict__ out)
{
    extern __shared__ char sm[];
    __half* As = (__half*)(sm + SM_A);
    __half* Bs = (__half*)(sm + SM_B);
    float*  bs = (float*)(sm + SM_BIAS);
    float*  cs = (float*)(sm + SM_CS);
    float*  hs = (float*)(sm + SM_HS);

    const int tid  = threadIdx.x;
    const int wid  = tid >> 5;
    const int lane = tid & 31;
    const int q    = lane & 3;
    const int gid  = lane >> 2;
    const int wm   = wid >> 2;       // 0..3, M block of 32 rows
    const int wn   = wid & 3;        // 0..3, N block of 64 cols

    const int nh     = blockIdx.x & 1;
    const int cidx   = blockIdx.x >> 1;
    const int npairs = gridDim.x >> 1;

    // ---- stage weights half + bias once ----
    {
        const uint32_t* wsrc = (const uint32_t*)g_W + nh * 18432;
        for (int i = tid; i < 256 * 72; i += NTHREADS) {
            int col = i / 72, kk = i - col * 72;
            *((uint32_t*)Bs + col * (PITCH / 2) + kk) = wsrc[col * 72 + kk];
        }
        for (int i = tid; i < 256; i += NTHREADS) bs[i] = g_bias[nh * 256 + i];
    }
    __syncthreads();

    // per-thread bias init (column-only)
    float binit[8][2];
    #pragma unroll
    for (int nt = 0; nt < 8; nt++) {
        binit[nt][0] = bs[wn * 64 + nt * 8 + 2 * q + 0];
        binit[nt][1] = bs[wn * 64 + nt * 8 + 2 * q + 1];
    }

    float* out_h  = out;
    float* out_h2 = out + (size_t)B_TOTAL * HDIM;
    float* out_c  = out + (size_t)2 * B_TOTAL * HDIM;

    for (int bt = cidx; bt < NBT; bt += npairs) {
        const int rowbase = bt * TILE_M;
        __syncthreads();   // prior tile fully consumed As/cs/hs

        // ---- A: h part (k 16..143) fp32 -> fp16 ----
        #pragma unroll
        for (int it = 0; it < 8; it++) {
            int i = tid + it * NTHREADS;
            int r = i >> 5, kq = i & 31;
            float4 v = ((const float4*)(h_in + (size_t)(rowbase + r) * HDIM))[kq];
            __half* ap = As + r * PITCH + 16 + kq * 4;
            *(__half2*)(ap)     = __floats2half2_rn(v.x, v.y);
            *(__half2*)(ap + 2) = __floats2half2_rn(v.z, v.w);
        }
        // ---- A: x part (k 0..15, 13 real + 3 zero) ----
        #pragma unroll
        for (int it = 0; it < 4; it++) {
            int i = tid + it * NTHREADS;
            int r = i >> 4, c = i & 15;
            float v = (c < INDIM) ? x_in[(size_t)(rowbase + r) * INDIM + c] : 0.f;
            As[r * PITCH + c] = __float2half_rn(v);
        }
        // ---- c preload (coalesced, vectorized staging) ----
        #pragma unroll
        for (int it = 0; it < 4; it++) {
            int i = tid + it * NTHREADS;
            int r = i >> 4, p4 = (i & 15) * 4;
            float4 v = *(const float4*)(c_in + (size_t)(rowbase + r) * HDIM + nh * 64 + p4);
            *(float4*)(cs + r * CPITCH + p4) = v;
        }
        __syncthreads();

        // ---- MMA: warp tile 32 rows x 64 cols, K = 144 ----
        float acc[2][8][4];
        #pragma unroll
        for (int mt = 0; mt < 2; mt++)
            #pragma unroll
            for (int nt = 0; nt < 8; nt++) {
                acc[mt][nt][0] = binit[nt][0];
                acc[mt][nt][1] = binit[nt][1];
                acc[mt][nt][2] = binit[nt][0];
                acc[mt][nt][3] = binit[nt][1];
            }

        #pragma unroll 1
        for (int ks = 0; ks < 9; ks++) {
            const int kb = ks * 16 + 2 * q;
            uint32_t af[2][4];
            #pragma unroll
            for (int mt = 0; mt < 2; mt++) {
                const __half* ap = As + (wm * 32 + mt * 16 + gid) * PITCH + kb;
                af[mt][0] = *(const uint32_t*)(ap);
                af[mt][1] = *(const uint32_t*)(ap + 8 * PITCH);
                af[mt][2] = *(const uint32_t*)(ap + 8);
                af[mt][3] = *(const uint32_t*)(ap + 8 * PITCH + 8);
            }
            uint32_t bf[8][2];
            #pragma unroll
            for (int nt = 0; nt < 8; nt++) {
                const __half* bp = Bs + (wn * 64 + nt * 8 + gid) * PITCH + kb;
                bf[nt][0] = *(const uint32_t*)(bp);
                bf[nt][1] = *(const uint32_t*)(bp + 8);
            }
            #pragma unroll
            for (int mt = 0; mt < 2; mt++)
                #pragma unroll
                for (int nt = 0; nt < 8; nt++) {
                    asm("mma.sync.aligned.m16n8k16.row.col.f32.f16.f16.f32 "
                        "{%0,%1,%2,%3}, {%4,%5,%6,%7}, {%8,%9}, {%0,%1,%2,%3};"
                        : "+f"(acc[mt][nt][0]), "+f"(acc[mt][nt][1]),
                          "+f"(acc[mt][nt][2]), "+f"(acc[mt][nt][3])
                        : "r"(af[mt][0]), "r"(af[mt][1]), "r"(af[mt][2]), "r"(af[mt][3]),
                          "r"(bf[nt][0]), "r"(bf[nt][1]));
                }
        }

        // ---- epilogue: all 4 gates of (row, j) in this thread ----
        #pragma unroll
        for (int mt = 0; mt < 2; mt++) {
            #pragma unroll
            for (int b = 0; b < 2; b++) {
                #pragma unroll
                for (int e = 0; e < 2; e++) {
                    const int jloc = wn * 16 + 8 * b + 2 * q + e;
                    #pragma unroll
                    for (int rs = 0; rs < 2; rs++) {
                        const int row = wm * 32 + mt * 16 + gid + 8 * rs;
                        const int ci  = rs * 2 + e;
                        float pi = acc[mt][0 + b][ci];
                        float pf = acc[mt][2 + b][ci];
                        float pg = acc[mt][4 + b][ci];
                        float po = acc[mt][6 + b][ci];
                        float it = fsig(pi), ft = fsig(pf), ot = fsig(po);
                        float gt = htanh(pg);
                        float ct = ft * cs[row * CPITCH + jloc] + it * gt;
                        float ht = ot * htanh(ct);
                        cs[row * CPITCH + jloc] = ct;
                        hs[row * CPITCH + jloc] = ht;
                    }
                }
            }
        }
        __syncthreads();

        // ---- coalesced float4 stores via staging ----
        #pragma unroll
        for (int it = 0; it < 4; it++) {
            int i = tid + it * NTHREADS;
            int r = i >> 4, p4 = (i & 15) * 4;
            float4 v = *(float4*)(hs + r * CPITCH + p4);
            float4 w = *(float4*)(cs + r * CPITCH + p4);
            size_t o = (size_t)(rowbase + r) * HDIM + nh * 64 + p4;
            *(float4*)(out_h + o)  = v;
            *(float4*)(out_h2 + o) = v;
            *(float4*)(out_c + o)  = w;
        }
    }
}

extern "C" void kernel_launch(void* const* d_in, const int* in_sizes, int n_in,
                              void* d_out, int out_size) {
    WP p;
    for (int g = 0; g < 4; g++) {
        p.Wx[g] = (const float*)d_in[3 + 4 * g];
        p.bx[g] = (const float*)d_in[4 + 4 * g];
        p.Wh[g] = (const float*)d_in[5 + 4 * g];
        p.bh[g] = (const float*)d_in[6 + 4 * g];
    }
    prep_kernel<<<(512 * 144 + 255) / 256, 256>>>(p);

    int dev = 0, sms = 0;
    cudaGetDevice(&dev);
    cudaDeviceGetAttribute(&sms, cudaDevAttrMultiProcessorCount, dev);
    if (sms <= 0) sms = 148;
    int grid = sms & ~1;
    cudaFuncSetAttribute(lstm_kernel, cudaFuncAttributeMaxDynamicSharedMemorySize, SMEM_BYTES);
    lstm_kernel<<<grid, NTHREADS, SMEM_BYTES>>>(
        (const float*)d_in[0], (const float*)d_in[1], (const float*)d_in[2], (float*)d_out);
}